// round 1
// baseline (speedup 1.0000x reference)
#include <cuda_runtime.h>
#include <cstdint>

// ============================================================================
// SequenceMemoryUpdater: out_mem = scatter(memory, ids, GRU(msg, memory[ids]))
//                        out_lu  = scatter(last_update, ids, timestamps)
//
// Structure:
//   kernel 1: bulk copy memory -> out_mem, last_update -> out_lu  (HBM-bound)
//   kernel 2: per 64-row tile: gates GEMM (tf32 mma.sync) + GRU epilogue,
//             scatter updated rows over the copy.
//
// GEMM formulation: gates[b, 0:512] where
//   cols   0..127 : r  pre-act = x@W_ih[0:128]^T   + h@W_hh[0:128]^T
//   cols 128..255 : z  pre-act = x@W_ih[128:256]^T + h@W_hh[128:256]^T
//   cols 256..383 : i_n        = x@W_ih[256:384]^T           (K = x half only)
//   cols 384..511 : h_n        = h@W_hh[256:384]^T           (K = h half only)
// K is chunked 12 x 32: chunks 0..7 = x (messages), 8..11 = h (gathered memory).
// ============================================================================

#define BLOCK_M   64
#define THREADS   512

// shared memory layout (float offsets)
#define ZS_OFF     0            // 64 x 36   (aliased under GATES)
#define WS_OFF     2304         // 384 x 36  (aliased under GATES)
#define GATES_OFF  0            // 64 x 520
#define HOLD_OFF   33280        // 64 x 132  (persistent h rows, fp32)
#define BIAS_OFF   41728        // 512: brz[256], bin[128], bhn[128]
#define IDS_OFF    42240        // 64 ints
#define SMEM_FLOATS 42304
#define SMEM_BYTES  (SMEM_FLOATS * 4)

__device__ __forceinline__ uint32_t f2tf32(float x) {
    uint32_t r;
    asm("cvt.rna.tf32.f32 %0, %1;" : "=r"(r) : "f"(x));
    return r;
}

__device__ __forceinline__ void mma_tf32(float* d, const uint32_t* a,
                                         uint32_t b0, uint32_t b1) {
    asm volatile(
        "mma.sync.aligned.m16n8k8.row.col.f32.tf32.tf32.f32 "
        "{%0,%1,%2,%3}, {%4,%5,%6,%7}, {%8,%9}, {%0,%1,%2,%3};"
        : "+f"(d[0]), "+f"(d[1]), "+f"(d[2]), "+f"(d[3])
        : "r"(a[0]), "r"(a[1]), "r"(a[2]), "r"(a[3]), "r"(b0), "r"(b1));
}

__device__ __forceinline__ float gru_one(float pr, float pz, float pin,
                                         float phn, float h) {
    float r = 1.0f / (1.0f + __expf(-pr));
    float z = 1.0f / (1.0f + __expf(-pz));
    float n = tanhf(fmaf(r, phn, pin));
    return fmaf(z, h - n, n);   // (1-z)*n + z*h
}

// ---------------------------------------------------------------------------
// Kernel 1: bulk copy (memory || last_update) -> out, vectorized float4
// ---------------------------------------------------------------------------
__global__ void copy_all_kernel(const float4* __restrict__ mem,
                                const float4* __restrict__ lu,
                                float4* __restrict__ out,
                                long long n4m, long long n4tot) {
    long long i = (long long)blockIdx.x * blockDim.x + threadIdx.x;
    if (i < n4tot) {
        out[i] = (i < n4m) ? mem[i] : lu[i - n4m];
    }
}

// ---------------------------------------------------------------------------
// Kernel 2: fused gather + gates GEMM + GRU epilogue + scatter
// ---------------------------------------------------------------------------
__global__ void __launch_bounds__(THREADS, 1)
gru_update_kernel(const float* __restrict__ memory,
                  const int*   __restrict__ ids,
                  const float* __restrict__ messages,
                  const float* __restrict__ ts,
                  const float* __restrict__ W_ih,
                  const float* __restrict__ W_hh,
                  const float* __restrict__ b_ih,
                  const float* __restrict__ b_hh,
                  float* __restrict__ out_mem,
                  float* __restrict__ out_lu,
                  int B) {
    extern __shared__ float sm[];
    const int tid  = threadIdx.x;
    const int lane = tid & 31;
    const int warp = tid >> 5;
    const int row0 = blockIdx.x * BLOCK_M;

    int* ids_s = (int*)(sm + IDS_OFF);

    // ---- phase 0: ids + fused biases ----
    if (tid < BLOCK_M) {
        int gr = row0 + tid;
        ids_s[tid] = (gr < B) ? ids[gr] : 0;
    }
    if (tid < 256)      sm[BIAS_OFF + tid] = b_ih[tid] + b_hh[tid];  // brz
    else if (tid < 384) sm[BIAS_OFF + tid] = b_ih[tid];              // bin
    else                sm[BIAS_OFF + tid] = b_hh[tid - 128];        // bhn
    __syncthreads();

    // ---- gather h rows into persistent hold (fp32, reused as A-operand) ----
    {
        int m = tid >> 3;
        int c = (tid & 7) << 4;
        const float4* src = (const float4*)(memory + (size_t)ids_s[m] * 128 + c);
        float4* dst = (float4*)(sm + HOLD_OFF + m * 132 + c);
#pragma unroll
        for (int i = 0; i < 4; ++i) dst[i] = src[i];
    }

    // warp tiling: 2 warps over M (32 rows each), 8 over N (64 cols each)
    const int wm = warp & 1;
    const int wn8 = warp >> 1;
    const int g  = wn8 >> 1;        // 0=r, 1=z, 2=i_n, 3=h_n
    const int ch = wn8 & 1;         // column half within gate
    const int nrow0 = ((g < 2) ? g : 2) * 128 + ch * 64;  // row base in Ws

    float acc[2][8][4];
#pragma unroll
    for (int mt = 0; mt < 2; ++mt)
#pragma unroll
        for (int nt = 0; nt < 8; ++nt)
#pragma unroll
            for (int c = 0; c < 4; ++c) acc[mt][nt][c] = 0.0f;

    // ---- K loop: 12 chunks of 32 ----
    for (int kc = 0; kc < 12; ++kc) {
        __syncthreads();  // prior chunk consumed (also covers hold-load on kc=0)

        // stage W chunk (tf32-rounded at load; rows 0..383 of the active half)
        {
            const float* W = (kc < 8) ? W_ih : W_hh;
            const int stride = (kc < 8) ? 256 : 128;
            const int col0   = (kc < 8) ? kc * 32 : (kc - 8) * 32;
            for (int i = tid; i < 3072; i += THREADS) {   // 384*32/4 float4s
                int r = i >> 3, c4 = (i & 7) << 2;
                float4 v = *(const float4*)(W + (size_t)r * stride + col0 + c4);
                float* d = sm + WS_OFF + r * 36 + c4;
                d[0] = __uint_as_float(f2tf32(v.x));
                d[1] = __uint_as_float(f2tf32(v.y));
                d[2] = __uint_as_float(f2tf32(v.z));
                d[3] = __uint_as_float(f2tf32(v.w));
            }
        }
        // stage message chunk (x half of K only)
        if (kc < 8) {
            int m = tid >> 3, c4 = (tid & 7) << 2;
            int gr = row0 + m;
            float4 v = make_float4(0.f, 0.f, 0.f, 0.f);
            if (gr < B)
                v = *(const float4*)(messages + (size_t)gr * 256 + kc * 32 + c4);
            float* d = sm + ZS_OFF + m * 36 + c4;
            d[0] = v.x; d[1] = v.y; d[2] = v.z; d[3] = v.w;
        }
        __syncthreads();

        const bool active = (g < 2) || (g == 2 && kc < 8) || (g == 3 && kc >= 8);
        if (active) {
            const float* A;
            int As, Ac;
            if (kc < 8) { A = sm + ZS_OFF;   As = 36;  Ac = 0; }
            else        { A = sm + HOLD_OFF; As = 132; Ac = (kc - 8) * 32; }
            const uint32_t* Wsu = (const uint32_t*)(sm + WS_OFF);

#pragma unroll
            for (int k8 = 0; k8 < 4; ++k8) {
                uint32_t a[2][4];
#pragma unroll
                for (int mt = 0; mt < 2; ++mt) {
                    const float* ap = A + (wm * 32 + mt * 16 + (lane >> 2)) * As
                                        + Ac + k8 * 8 + (lane & 3);
                    a[mt][0] = f2tf32(ap[0]);
                    a[mt][1] = f2tf32(ap[8 * As]);
                    a[mt][2] = f2tf32(ap[4]);
                    a[mt][3] = f2tf32(ap[8 * As + 4]);
                }
#pragma unroll
                for (int nt = 0; nt < 8; ++nt) {
                    const uint32_t* bp = Wsu + (nrow0 + nt * 8 + (lane >> 2)) * 36
                                             + k8 * 8 + (lane & 3);
                    uint32_t b0 = bp[0], b1 = bp[4];
                    mma_tf32(acc[0][nt], a[0], b0, b1);
                    mma_tf32(acc[1][nt], a[1], b0, b1);
                }
            }
        }
    }

    // ---- exchange gates through shared (tiles region is dead now) ----
    __syncthreads();
#pragma unroll
    for (int mt = 0; mt < 2; ++mt) {
        int rbase = wm * 32 + mt * 16 + (lane >> 2);
        int hbase = ch * 64 + (lane & 3) * 2;
#pragma unroll
        for (int nt = 0; nt < 8; ++nt) {
            float* p = sm + GATES_OFF + rbase * 520 + g * 128 + hbase + nt * 8;
            *(float2*)p             = make_float2(acc[mt][nt][0], acc[mt][nt][1]);
            *(float2*)(p + 8 * 520) = make_float2(acc[mt][nt][2], acc[mt][nt][3]);
        }
    }
    __syncthreads();

    // ---- GRU epilogue + scatter: thread -> (row, 16 h-cols) ----
    {
        int row_l = tid >> 3;
        int h0 = (tid & 7) << 4;
        int gr = row0 + row_l;
        if (gr < B) {
            int node = ids_s[row_l];
            const float* grow = sm + GATES_OFF + row_l * 520;
            const float* hrow = sm + HOLD_OFF + row_l * 132;
            float* orow = out_mem + (size_t)node * 128;
#pragma unroll
            for (int i = 0; i < 4; ++i) {
                int hb = h0 + i * 4;
                float4 pr  = *(const float4*)(grow + hb);
                float4 pz  = *(const float4*)(grow + 128 + hb);
                float4 pin = *(const float4*)(grow + 256 + hb);
                float4 phn = *(const float4*)(grow + 384 + hb);
                float4 ho  = *(const float4*)(hrow + hb);
                float4 brz0 = *(const float4*)(sm + BIAS_OFF + hb);
                float4 brz1 = *(const float4*)(sm + BIAS_OFF + 128 + hb);
                float4 bin4 = *(const float4*)(sm + BIAS_OFF + 256 + hb);
                float4 bhn4 = *(const float4*)(sm + BIAS_OFF + 384 + hb);
                float4 res;
                res.x = gru_one(pr.x + brz0.x, pz.x + brz1.x, pin.x + bin4.x, phn.x + bhn4.x, ho.x);
                res.y = gru_one(pr.y + brz0.y, pz.y + brz1.y, pin.y + bin4.y, phn.y + bhn4.y, ho.y);
                res.z = gru_one(pr.z + brz0.z, pz.z + brz1.z, pin.z + bin4.z, phn.z + bhn4.z, ho.z);
                res.w = gru_one(pr.w + brz0.w, pz.w + brz1.w, pin.w + bin4.w, phn.w + bhn4.w, ho.w);
                *(float4*)(orow + hb) = res;
            }
            if ((tid & 7) == 0) out_lu[node] = ts[gr];
        }
    }
}

// ---------------------------------------------------------------------------
extern "C" void kernel_launch(void* const* d_in, const int* in_sizes, int n_in,
                              void* d_out, int out_size) {
    const float* memory      = (const float*)d_in[0];
    const float* last_update = (const float*)d_in[1];
    const int*   ids         = (const int*)d_in[2];
    const float* messages    = (const float*)d_in[3];
    const float* ts          = (const float*)d_in[4];
    const float* W_ih        = (const float*)d_in[5];
    const float* W_hh        = (const float*)d_in[6];
    const float* b_ih        = (const float*)d_in[7];
    const float* b_hh        = (const float*)d_in[8];

    const int n_nodes = in_sizes[1];   // last_update element count
    const int B       = in_sizes[2];   // number of updates

    float* out_mem = (float*)d_out;
    float* out_lu  = out_mem + (size_t)n_nodes * 128;

    // kernel 1: bulk copy
    long long n4m = (long long)n_nodes * 32;   // memory float4 count
    long long n4tot = n4m + n_nodes / 4;       // + last_update float4 count
    int cthreads = 256;
    long long cblocks = (n4tot + cthreads - 1) / cthreads;
    copy_all_kernel<<<(unsigned)cblocks, cthreads>>>(
        (const float4*)memory, (const float4*)last_update,
        (float4*)d_out, n4m, n4tot);

    // kernel 2: GRU update + scatter (after copy in-stream)
    cudaFuncSetAttribute(gru_update_kernel,
                         cudaFuncAttributeMaxDynamicSharedMemorySize, SMEM_BYTES);
    int tiles = (B + BLOCK_M - 1) / BLOCK_M;
    gru_update_kernel<<<tiles, THREADS, SMEM_BYTES>>>(
        memory, ids, messages, ts, W_ih, W_hh, b_ih, b_hh,
        out_mem, out_lu, B);
}

// round 2
// speedup vs baseline: 1.7135x; 1.7135x over previous
#include <cuda_runtime.h>
#include <cstdint>

// ============================================================================
// SequenceMemoryUpdater v2
//   kernel 1: bulk copy (memory || last_update) -> out          (HBM-bound)
//   kernel 2: per 64-row tile: gather h, gates GEMM (tf32 mma.sync, raw-fp32
//             operands = HW truncation), register-resident GRU epilogue,
//             scatter. cp.async double-buffered K-pipeline.
//
// gates[b, 0:512]: cols 0..127 r, 128..255 z, 256..383 i_n (x-K only),
//                  384..511 h_n (h-K only).
// K chunks 12 x 32: 0..7 = messages (K=256), 8..11 = gathered h (K=128).
// Warp mapping (16 warps): wm = warp&1 (32-row half), wq = warp>>1 (16 h-cols
// across ALL gates) -> every warp active every chunk, epilogue needs no
// cross-warp gate exchange.
// ============================================================================

#define BLOCK_M   64
#define THREADS   512

// shared memory layout (float offsets)
#define ZS0_OFF    0            // 64 x 36 A tile, buf 0
#define ZS1_OFF    2304         // 64 x 36 A tile, buf 1
#define WS0_OFF    4608         // 384 x 36 W tile, buf 0
#define WS1_OFF    18432        // 384 x 36 W tile, buf 1
#define HOLD_OFF   32256        // 64 x 132 persistent h rows (fp32)
#define BIAS_OFF   40704        // 512: brz[256], bin[128], bhn[128]
#define IDS_OFF    41216        // 64 ints
#define SMEM_FLOATS 41280
#define SMEM_BYTES  (SMEM_FLOATS * 4)

__device__ __forceinline__ void cp16(float* dst_smem, const float* src) {
    uint32_t d = (uint32_t)__cvta_generic_to_shared(dst_smem);
    asm volatile("cp.async.cg.shared.global [%0], [%1], 16;\n"
                 :: "r"(d), "l"(src));
}
#define CP_COMMIT() asm volatile("cp.async.commit_group;\n" ::: "memory")
#define CP_WAIT(N)  asm volatile("cp.async.wait_group %0;\n" :: "n"(N) : "memory")

// raw fp32 bits fed as tf32 (HW truncates low 13 mantissa bits)
__device__ __forceinline__ void mma_tf32(float* d, const float* a,
                                         float b0, float b1) {
    asm volatile(
        "mma.sync.aligned.m16n8k8.row.col.f32.tf32.tf32.f32 "
        "{%0,%1,%2,%3}, {%4,%5,%6,%7}, {%8,%9}, {%0,%1,%2,%3};"
        : "+f"(d[0]), "+f"(d[1]), "+f"(d[2]), "+f"(d[3])
        : "r"(__float_as_uint(a[0])), "r"(__float_as_uint(a[1])),
          "r"(__float_as_uint(a[2])), "r"(__float_as_uint(a[3])),
          "r"(__float_as_uint(b0)),  "r"(__float_as_uint(b1)));
}

__device__ __forceinline__ float gru_one(float pr, float pz, float pin,
                                         float phn, float h) {
    float r = 1.0f / (1.0f + __expf(-pr));
    float z = 1.0f / (1.0f + __expf(-pz));
    float n = tanhf(fmaf(r, phn, pin));
    return fmaf(z, h - n, n);   // (1-z)*n + z*h
}

// ---------------------------------------------------------------------------
// Kernel 1: bulk copy (memory || last_update) -> out, vectorized float4
// ---------------------------------------------------------------------------
__global__ void copy_all_kernel(const float4* __restrict__ mem,
                                const float4* __restrict__ lu,
                                float4* __restrict__ out,
                                long long n4m, long long n4tot) {
    long long i = (long long)blockIdx.x * blockDim.x + threadIdx.x;
    if (i < n4tot) {
        out[i] = (i < n4m) ? mem[i] : lu[i - n4m];
    }
}

// ---------------------------------------------------------------------------
// stage one K-chunk (W tile always; message A tile for kc<8) via cp.async
// ---------------------------------------------------------------------------
__device__ __forceinline__ void stage_chunk(float* sm, int kc, int row0,
                                            const float* __restrict__ messages,
                                            const float* __restrict__ W_ih,
                                            const float* __restrict__ W_hh,
                                            int B, int tid) {
    const int buf = kc & 1;
    float* ws = sm + (buf ? WS1_OFF : WS0_OFF);
    const float* W = (kc < 8) ? W_ih : W_hh;
    const int stride = (kc < 8) ? 256 : 128;
    const int col0   = (kc < 8) ? kc * 32 : (kc - 8) * 32;
#pragma unroll
    for (int i = 0; i < 6; ++i) {           // 3072 cp16 ops / 512 threads
        int idx = tid + i * THREADS;
        int r = idx >> 3, c4 = (idx & 7) << 2;
        cp16(ws + r * 36 + c4, W + (size_t)r * stride + col0 + c4);
    }
    if (kc < 8) {
        float* zs = sm + (buf ? ZS1_OFF : ZS0_OFF);
        int m = tid >> 3, c4 = (tid & 7) << 2;
        int gr = row0 + m; if (gr >= B) gr = B - 1;
        cp16(zs + m * 36 + c4, messages + (size_t)gr * 256 + kc * 32 + c4);
    }
}

// ---------------------------------------------------------------------------
// per-chunk MMA body; G2 = accumulator slot for the third gate (2=i_n, 3=h_n),
// AS = A-tile row stride in floats (compile-time so acc indices stay constant)
// ---------------------------------------------------------------------------
template<int G2, int AS>
__device__ __forceinline__ void mma_chunk(float (&acc)[2][4][2][4],
                                          const float* A, int Ac,
                                          const float* Ws,
                                          int wm, int wq, int lane) {
    const float* arow = A + (wm * 32 + (lane >> 2)) * AS + Ac + (lane & 3);
    const float* bbas = Ws + (wq * 16 + (lane >> 2)) * 36 + (lane & 3);
#pragma unroll
    for (int k8 = 0; k8 < 4; ++k8) {
        float a[2][4];
#pragma unroll
        for (int mt = 0; mt < 2; ++mt) {
            const float* ap = arow + mt * 16 * AS + k8 * 8;
            a[mt][0] = ap[0];
            a[mt][1] = ap[8 * AS];
            a[mt][2] = ap[4];
            a[mt][3] = ap[8 * AS + 4];
        }
#pragma unroll
        for (int gate = 0; gate < 3; ++gate) {
            const int gi = (gate == 2) ? G2 : gate;
#pragma unroll
            for (int sub = 0; sub < 2; ++sub) {
                const float* bp = bbas + (gate * 128 + sub * 8) * 36 + k8 * 8;
                float b0 = bp[0], b1 = bp[4];
                mma_tf32(acc[0][gi][sub], a[0], b0, b1);
                mma_tf32(acc[1][gi][sub], a[1], b0, b1);
            }
        }
    }
}

// ---------------------------------------------------------------------------
// Kernel 2: fused gather + gates GEMM + GRU epilogue + scatter
// ---------------------------------------------------------------------------
__global__ void __launch_bounds__(THREADS, 1)
gru_update_kernel(const float* __restrict__ memory,
                  const int*   __restrict__ ids,
                  const float* __restrict__ messages,
                  const float* __restrict__ ts,
                  const float* __restrict__ W_ih,
                  const float* __restrict__ W_hh,
                  const float* __restrict__ b_ih,
                  const float* __restrict__ b_hh,
                  float* __restrict__ out_mem,
                  float* __restrict__ out_lu,
                  int B) {
    extern __shared__ float sm[];
    const int tid  = threadIdx.x;
    const int lane = tid & 31;
    const int warp = tid >> 5;
    const int row0 = blockIdx.x * BLOCK_M;
    const int wm = warp & 1;       // 32-row half
    const int wq = warp >> 1;      // 16-h-col group (same cols in all gates)

    int* ids_s = (int*)(sm + IDS_OFF);

    // ---- phase 0: ids + fused biases ----
    if (tid < BLOCK_M) {
        int gr = row0 + tid;
        ids_s[tid] = (gr < B) ? ids[gr] : 0;
    }
    if (tid < 256)      sm[BIAS_OFF + tid] = b_ih[tid] + b_hh[tid];  // r,z
    else if (tid < 384) sm[BIAS_OFF + tid] = b_ih[tid];              // i_n
    else                sm[BIAS_OFF + tid] = b_hh[tid - 128];        // h_n
    __syncthreads();

    // ---- issue async: h-row gather + chunk 0 (group 0), chunk 1 (group 1) ----
#pragma unroll
    for (int i = 0; i < 4; ++i) {          // 2048 cp16 ops for HOLD
        int idx = tid + i * THREADS;
        int m = idx >> 5, c4 = (idx & 31) << 2;
        cp16(sm + HOLD_OFF + m * 132 + c4,
             memory + (size_t)ids_s[m] * 128 + c4);
    }
    stage_chunk(sm, 0, row0, messages, W_ih, W_hh, B, tid);
    CP_COMMIT();
    stage_chunk(sm, 1, row0, messages, W_ih, W_hh, B, tid);
    CP_COMMIT();

    float acc[2][4][2][4];                 // [mt][gate r/z/in/hn][sub][c]
#pragma unroll
    for (int mt = 0; mt < 2; ++mt)
#pragma unroll
        for (int g = 0; g < 4; ++g)
#pragma unroll
            for (int s = 0; s < 2; ++s)
#pragma unroll
                for (int c = 0; c < 4; ++c) acc[mt][g][s][c] = 0.0f;

    // ---- x chunks: kc = 0..7 (A = messages tile, third gate = i_n) ----
    for (int kc = 0; kc < 8; ++kc) {
        CP_WAIT(1);
        __syncthreads();
        const int buf = kc & 1;
        mma_chunk<2, 36>(acc, sm + (buf ? ZS1_OFF : ZS0_OFF), 0,
                         sm + (buf ? WS1_OFF : WS0_OFF), wm, wq, lane);
        __syncthreads();
        stage_chunk(sm, kc + 2, row0, messages, W_ih, W_hh, B, tid);
        CP_COMMIT();
    }
    // ---- h chunks: kc = 8..11 (A = HOLD, third gate = h_n) ----
    for (int kc = 8; kc < 12; ++kc) {
        if (kc == 11) { CP_WAIT(0); } else { CP_WAIT(1); }
        __syncthreads();
        const int buf = kc & 1;
        mma_chunk<3, 132>(acc, sm + HOLD_OFF, (kc - 8) * 32,
                          sm + (buf ? WS1_OFF : WS0_OFF), wm, wq, lane);
        __syncthreads();
        if (kc < 10) {
            stage_chunk(sm, kc + 2, row0, messages, W_ih, W_hh, B, tid);
            CP_COMMIT();
        }
    }

    // ---- register-resident GRU epilogue + scatter ----
#pragma unroll
    for (int mt = 0; mt < 2; ++mt) {
#pragma unroll
        for (int half = 0; half < 2; ++half) {     // c{0,1} vs c{2,3}
            int row_l = wm * 32 + mt * 16 + (lane >> 2) + half * 8;
            int gr = row0 + row_l;
            int node = ids_s[row_l];
            const float* hrow = sm + HOLD_OFF + row_l * 132;
            float* orow = out_mem + (size_t)node * 128;
            const int c0 = half * 2;
#pragma unroll
            for (int sub = 0; sub < 2; ++sub) {
                int hc = wq * 16 + sub * 8 + (lane & 3) * 2;
                float2 ho = *(const float2*)(hrow + hc);
                float2 br = *(const float2*)(sm + BIAS_OFF + hc);
                float2 bz = *(const float2*)(sm + BIAS_OFF + 128 + hc);
                float2 bi = *(const float2*)(sm + BIAS_OFF + 256 + hc);
                float2 bh = *(const float2*)(sm + BIAS_OFF + 384 + hc);
                float2 res;
                res.x = gru_one(acc[mt][0][sub][c0]     + br.x,
                                acc[mt][1][sub][c0]     + bz.x,
                                acc[mt][2][sub][c0]     + bi.x,
                                acc[mt][3][sub][c0]     + bh.x, ho.x);
                res.y = gru_one(acc[mt][0][sub][c0 + 1] + br.y,
                                acc[mt][1][sub][c0 + 1] + bz.y,
                                acc[mt][2][sub][c0 + 1] + bi.y,
                                acc[mt][3][sub][c0 + 1] + bh.y, ho.y);
                if (gr < B) *(float2*)(orow + hc) = res;
            }
        }
    }
    if (tid < BLOCK_M) {
        int gr = row0 + tid;
        if (gr < B) out_lu[ids_s[tid]] = ts[gr];
    }
}

// ---------------------------------------------------------------------------
extern "C" void kernel_launch(void* const* d_in, const int* in_sizes, int n_in,
                              void* d_out, int out_size) {
    const float* memory      = (const float*)d_in[0];
    const float* last_update = (const float*)d_in[1];
    const int*   ids         = (const int*)d_in[2];
    const float* messages    = (const float*)d_in[3];
    const float* ts          = (const float*)d_in[4];
    const float* W_ih        = (const float*)d_in[5];
    const float* W_hh        = (const float*)d_in[6];
    const float* b_ih        = (const float*)d_in[7];
    const float* b_hh        = (const float*)d_in[8];

    const int n_nodes = in_sizes[1];   // last_update element count
    const int B       = in_sizes[2];   // number of updates

    float* out_mem = (float*)d_out;
    float* out_lu  = out_mem + (size_t)n_nodes * 128;

    // kernel 1: bulk copy
    long long n4m = (long long)n_nodes * 32;   // memory float4 count
    long long n4tot = n4m + n_nodes / 4;       // + last_update float4 count
    int cthreads = 256;
    long long cblocks = (n4tot + cthreads - 1) / cthreads;
    copy_all_kernel<<<(unsigned)cblocks, cthreads>>>(
        (const float4*)memory, (const float4*)last_update,
        (float4*)d_out, n4m, n4tot);

    // kernel 2: GRU update + scatter
    static int smem_set = 0;
    if (!smem_set) {
        cudaFuncSetAttribute(gru_update_kernel,
                             cudaFuncAttributeMaxDynamicSharedMemorySize,
                             SMEM_BYTES);
        smem_set = 1;
    }
    int tiles = (B + BLOCK_M - 1) / BLOCK_M;
    gru_update_kernel<<<tiles, THREADS, SMEM_BYTES>>>(
        memory, ids, messages, ts, W_ih, W_hh, b_ih, b_hh,
        out_mem, out_lu, B);
}